// round 1
// baseline (speedup 1.0000x reference)
#include <cuda_runtime.h>
#include <math.h>

// Problem constants (fixed shapes from setup_inputs)
#define BB   16
#define DIM  384
#define NHKD 256
#define DHV  1024
#define NTOK 1024
#define NH   8
#define KDIM 32
#define DV   128

// Scratch (device globals — no allocations allowed)
__device__ float g_q [BB * NHKD * NTOK];
__device__ float g_k [BB * NHKD * NTOK];
__device__ float g_v [BB * DHV  * NTOK];
__device__ float g_xx[BB * DHV  * NTOK];

// ---------------------------------------------------------------------------
// GEMM + BN:  Y[b][m][n] = (sum_k W[m][k] * X[b][k][n]) * s[m] + t[m]
//   s = gamma * rsqrt(var + 1e-5), t = beta - mean * s
// Tile 64(M) x 64(N), K-tile 16, 256 threads, 4x4 per thread. N fixed = 1024.
// ---------------------------------------------------------------------------
__global__ __launch_bounds__(256) void gemm_bn_kernel(
    const float* __restrict__ W, const float* __restrict__ bn,
    const float* __restrict__ X, float* __restrict__ Y,
    int M, int K, long xStride, long yStride)
{
    __shared__ float As[16 * 65];   // [k][m], padded
    __shared__ float Bs[16 * 64];   // [k][n]

    const int t  = threadIdx.x;
    const int tx = t & 15, ty = t >> 4;
    const int n0 = blockIdx.x * 64;
    const int m0 = blockIdx.y * 64;
    const float* Xb = X + (long)blockIdx.z * xStride;
    float*       Yb = Y + (long)blockIdx.z * yStride;

    const int ar = t >> 2, ak = (t & 3) * 4;     // A loader: row ar (64), k-chunk ak
    const int bk = t >> 4, bnn = (t & 15) * 4;   // B loader: k-row bk (16), n-chunk

    float c[4][4];
#pragma unroll
    for (int i = 0; i < 4; i++)
#pragma unroll
        for (int j = 0; j < 4; j++) c[i][j] = 0.f;

    for (int kt = 0; kt < K; kt += 16) {
        float4 wv4 = *(const float4*)(W + (long)(m0 + ar) * K + kt + ak);
        float4 xv4 = *(const float4*)(Xb + (long)(kt + bk) * NTOK + n0 + bnn);
        __syncthreads();   // previous compute done reading smem
        As[(ak + 0) * 65 + ar] = wv4.x;
        As[(ak + 1) * 65 + ar] = wv4.y;
        As[(ak + 2) * 65 + ar] = wv4.z;
        As[(ak + 3) * 65 + ar] = wv4.w;
        *(float4*)(Bs + bk * 64 + bnn) = xv4;
        __syncthreads();
#pragma unroll
        for (int kk = 0; kk < 16; kk++) {
            float a0 = As[kk * 65 + ty * 4 + 0];
            float a1 = As[kk * 65 + ty * 4 + 1];
            float a2 = As[kk * 65 + ty * 4 + 2];
            float a3 = As[kk * 65 + ty * 4 + 3];
            float4 b4 = *(float4*)(Bs + kk * 64 + tx * 4);
            c[0][0] += a0 * b4.x; c[0][1] += a0 * b4.y; c[0][2] += a0 * b4.z; c[0][3] += a0 * b4.w;
            c[1][0] += a1 * b4.x; c[1][1] += a1 * b4.y; c[1][2] += a1 * b4.z; c[1][3] += a1 * b4.w;
            c[2][0] += a2 * b4.x; c[2][1] += a2 * b4.y; c[2][2] += a2 * b4.z; c[2][3] += a2 * b4.w;
            c[3][0] += a3 * b4.x; c[3][1] += a3 * b4.y; c[3][2] += a3 * b4.z; c[3][3] += a3 * b4.w;
        }
    }

#pragma unroll
    for (int i = 0; i < 4; i++) {
        int m = m0 + ty * 4 + i;
        float g  = bn[0 * M + m];
        float be = bn[1 * M + m];
        float mu = bn[2 * M + m];
        float va = bn[3 * M + m];
        float sc = g * rsqrtf(va + 1e-5f);
        float tt = be - mu * sc;
        float4 r;
        r.x = c[i][0] * sc + tt;
        r.y = c[i][1] * sc + tt;
        r.z = c[i][2] * sc + tt;
        r.w = c[i][3] * sc + tt;
        *(float4*)(Yb + (long)m * NTOK + n0 + tx * 4) = r;
    }
}

// ---------------------------------------------------------------------------
// Fused flash attention per (b, h, 64-query tile).
//   S = (Q^T K) * sqrt(kd)   [reference divides by kd^-0.5]
//   online softmax over N=1024 keys, O = softmax(S) @ V^T
// q,k stored [kd][n]; v stored [d][n]. Output written to g_xx[b][h*128+d][n].
// 256 threads = 16x16; each thread: 4 query rows x (4 S cols / 8 d cols).
// ---------------------------------------------------------------------------
__global__ __launch_bounds__(256) void attn_kernel()
{
    extern __shared__ float sm[];
    float* Qs = sm;             // 32 x 64
    float* Ks = Qs + 32 * 64;   // 32 x 64
    float* Ps = Ks + 32 * 64;   // 64 x 64
    float* Vs = Ps + 64 * 64;   // 128 x 65 (padded)

    const int t  = threadIdx.x;
    const int tx = t & 15, ty = t >> 4;
    const int q0 = blockIdx.x * 64;
    const int bh = blockIdx.y;
    const int b  = bh >> 3, h = bh & 7;

    const float* qp = g_q + (long)b * NHKD * NTOK + (long)h * KDIM * NTOK;
    const float* kp = g_k + (long)b * NHKD * NTOK + (long)h * KDIM * NTOK;
    const float* vp = g_v + (long)b * DHV  * NTOK + (long)h * DV   * NTOK;

    const float scale = 5.656854249492380f;  // sqrt(32)

    // Load Q tile [32][64], pre-scaled
    {
        int r = t >> 4, c4 = (t & 15) * 4;
#pragma unroll
        for (int p = 0; p < 2; p++) {
            float4 v4 = *(const float4*)(qp + (long)(r + 16 * p) * NTOK + q0 + c4);
            float* dst = Qs + (r + 16 * p) * 64 + c4;
            dst[0] = v4.x * scale; dst[1] = v4.y * scale;
            dst[2] = v4.z * scale; dst[3] = v4.w * scale;
        }
    }

    float m_i[4], l_i[4], o[4][8];
#pragma unroll
    for (int i = 0; i < 4; i++) {
        m_i[i] = -1e30f; l_i[i] = 0.f;
#pragma unroll
        for (int d = 0; d < 8; d++) o[i][d] = 0.f;
    }

    for (int jt = 0; jt < 16; jt++) {
        const int j0 = jt * 64;
        __syncthreads();  // prev AV done reading Ps/Vs (also covers Q store on iter 0)
        // Load K tile [32][64] and V tile [128][64->65]
        {
            int r = t >> 4, c4 = (t & 15) * 4;
#pragma unroll
            for (int p = 0; p < 2; p++) {
                float4 v4 = *(const float4*)(kp + (long)(r + 16 * p) * NTOK + j0 + c4);
                *(float4*)(Ks + (r + 16 * p) * 64 + c4) = v4;
            }
#pragma unroll
            for (int p = 0; p < 8; p++) {
                int d = r + 16 * p;
                float4 v4 = *(const float4*)(vp + (long)d * NTOK + j0 + c4);
                float* dst = Vs + d * 65 + c4;
                dst[0] = v4.x; dst[1] = v4.y; dst[2] = v4.z; dst[3] = v4.w;
            }
        }
        __syncthreads();

        // S tile: rows r = ty*4+i, cols j = tx*4+j
        float s[4][4];
#pragma unroll
        for (int i = 0; i < 4; i++)
#pragma unroll
            for (int j = 0; j < 4; j++) s[i][j] = 0.f;

#pragma unroll 8
        for (int kd = 0; kd < 32; kd++) {
            float4 qa = *(float4*)(Qs + kd * 64 + ty * 4);
            float4 kb = *(float4*)(Ks + kd * 64 + tx * 4);
            float aa[4] = {qa.x, qa.y, qa.z, qa.w};
            float bb[4] = {kb.x, kb.y, kb.z, kb.w};
#pragma unroll
            for (int i = 0; i < 4; i++)
#pragma unroll
                for (int j = 0; j < 4; j++) s[i][j] += aa[i] * bb[j];
        }

        // Online softmax update (row groups span 16 lanes sharing ty)
#pragma unroll
        for (int i = 0; i < 4; i++) {
            float tmax = fmaxf(fmaxf(s[i][0], s[i][1]), fmaxf(s[i][2], s[i][3]));
#pragma unroll
            for (int msk = 1; msk < 16; msk <<= 1)
                tmax = fmaxf(tmax, __shfl_xor_sync(0xffffffffu, tmax, msk));
            float mnew  = fmaxf(m_i[i], tmax);
            float alpha = __expf(m_i[i] - mnew);
            m_i[i] = mnew;
            float rs = 0.f;
#pragma unroll
            for (int j = 0; j < 4; j++) { s[i][j] = __expf(s[i][j] - mnew); rs += s[i][j]; }
#pragma unroll
            for (int msk = 1; msk < 16; msk <<= 1)
                rs += __shfl_xor_sync(0xffffffffu, rs, msk);
            l_i[i] = l_i[i] * alpha + rs;
#pragma unroll
            for (int d = 0; d < 8; d++) o[i][d] *= alpha;
        }

        // Stage P
#pragma unroll
        for (int i = 0; i < 4; i++)
            *(float4*)(Ps + (ty * 4 + i) * 64 + tx * 4) =
                make_float4(s[i][0], s[i][1], s[i][2], s[i][3]);
        __syncthreads();

        // O += P @ V^T : thread owns rows ty*4+i, d-cols tx+16*ds
#pragma unroll 4
        for (int jj = 0; jj < 64; jj++) {
            float p0 = Ps[(ty * 4 + 0) * 64 + jj];
            float p1 = Ps[(ty * 4 + 1) * 64 + jj];
            float p2 = Ps[(ty * 4 + 2) * 64 + jj];
            float p3 = Ps[(ty * 4 + 3) * 64 + jj];
#pragma unroll
            for (int ds = 0; ds < 8; ds++) {
                float vv = Vs[(tx + 16 * ds) * 65 + jj];
                o[0][ds] += p0 * vv;
                o[1][ds] += p1 * vv;
                o[2][ds] += p2 * vv;
                o[3][ds] += p3 * vv;
            }
        }
    }

    // Epilogue: normalize, transpose through smem, coalesced write to g_xx[d][n]
    __syncthreads();
#pragma unroll
    for (int i = 0; i < 4; i++) {
        float inv = 1.0f / l_i[i];
#pragma unroll
        for (int ds = 0; ds < 8; ds++)
            Vs[(tx + 16 * ds) * 65 + ty * 4 + i] = o[i][ds] * inv;
    }
    __syncthreads();
    float* xxp = g_xx + (long)b * DHV * NTOK + (long)h * DV * NTOK;
    {
        int r = t >> 4, c4 = (t & 15) * 4;
#pragma unroll
        for (int p = 0; p < 8; p++) {
            int d = r + 16 * p;
            float* src = Vs + d * 65 + c4;
            float4 v4;
            v4.x = src[0]; v4.y = src[1]; v4.z = src[2]; v4.w = src[3];
            *(float4*)(xxp + (long)d * NTOK + q0 + c4) = v4;
        }
    }
}

// ---------------------------------------------------------------------------
extern "C" void kernel_launch(void* const* d_in, const int* in_sizes, int n_in,
                              void* d_out, int out_size)
{
    const float* x   = (const float*)d_in[0];
    const float* wq  = (const float*)d_in[1];
    const float* bnq = (const float*)d_in[2];
    const float* wk  = (const float*)d_in[3];
    const float* bnk = (const float*)d_in[4];
    const float* wv  = (const float*)d_in[5];
    const float* bnv = (const float*)d_in[6];
    const float* wp  = (const float*)d_in[7];
    const float* bnp = (const float*)d_in[8];
    float* out = (float*)d_out;

    float *qs, *ks, *vs, *xxs;
    cudaGetSymbolAddress((void**)&qs,  g_q);
    cudaGetSymbolAddress((void**)&ks,  g_k);
    cudaGetSymbolAddress((void**)&vs,  g_v);
    cudaGetSymbolAddress((void**)&xxs, g_xx);

    const int smem_attn = (32 * 64 + 32 * 64 + 64 * 64 + 128 * 65) * 4;  // 66048 B
    cudaFuncSetAttribute(attn_kernel, cudaFuncAttributeMaxDynamicSharedMemorySize,
                         smem_attn);

    dim3 blk(256);

    // QKV projections
    gemm_bn_kernel<<<dim3(16, NHKD / 64, BB), blk>>>(
        wq, bnq, x, qs, NHKD, DIM, (long)DIM * NTOK, (long)NHKD * NTOK);
    gemm_bn_kernel<<<dim3(16, NHKD / 64, BB), blk>>>(
        wk, bnk, x, ks, NHKD, DIM, (long)DIM * NTOK, (long)NHKD * NTOK);
    gemm_bn_kernel<<<dim3(16, DHV / 64, BB), blk>>>(
        wv, bnv, x, vs, DHV, DIM, (long)DIM * NTOK, (long)DHV * NTOK);

    // Fused flash attention
    attn_kernel<<<dim3(16, BB * NH), blk, smem_attn>>>();

    // Output projection
    gemm_bn_kernel<<<dim3(16, DIM / 64, BB), blk>>>(
        wp, bnp, xxs, out, DIM, DHV, (long)DHV * NTOK, (long)DIM * NTOK);
}